// round 1
// baseline (speedup 1.0000x reference)
#include <cuda_runtime.h>
#include <cuda_bf16.h>

// 3D Gaussian splat: N=65536 points -> 256^3 fp32 volume, 7x7x7 window each.
// Layout of paras: (10, N) row-major: px,py,pz,val,rx,rxy,rxz,ry,ryz,rz.
// flat index = (vx*256 + vy)*256 + vz.

#define WIN 7
#define HALF 3
#define NPT 343          // WIN^3
#define DVOX 256

__global__ __launch_bounds__(352)
void splat_kernel(const float* __restrict__ paras,
                  const float* __restrict__ dptr,
                  const float* __restrict__ tptr,
                  float* __restrict__ out,
                  int N)
{
    const int pid = blockIdx.x;
    const int t   = threadIdx.x;
    if (pid >= N) return;

    // Broadcast loads of the point's 10 params (all threads same address -> L1 broadcast)
    const float px  = paras[0 * N + pid];
    const float py  = paras[1 * N + pid];
    const float pz  = paras[2 * N + pid];
    const float val = paras[3 * N + pid];
    const float rx  = paras[4 * N + pid];
    const float rxy = paras[5 * N + pid];
    const float rxz = paras[6 * N + pid];
    const float ry  = paras[7 * N + pid];
    const float ryz = paras[8 * N + pid];
    const float rz  = paras[9 * N + pid];

    const float dist = *dptr;
    const float thr  = *tptr;
    const float d2max = dist * dist;

    const float irx2 = __fdividef(1.0f, rx * rx);
    const float iry2 = __fdividef(1.0f, ry * ry);
    const float irz2 = __fdividef(1.0f, rz * rz);

    const int cx = (int)floorf(px) - HALF;
    const int cy = (int)floorf(py) - HALF;
    const int cz = (int)floorf(pz) - HALF;

    if (t < NPT) {
        const int ox  = t / 49;          // const-div -> mul/shift
        const int rem = t - ox * 49;
        const int oy  = rem / 7;
        const int oz  = rem - oy * 7;

        const int vx = cx + ox;
        const int vy = cy + oy;
        const int vz = cz + oz;

        const float dx = (float)vx - px;
        const float dy = (float)vy - py;
        const float dz = (float)vz - pz;

        const float dist2 = fmaf(dx, dx, fmaf(dy, dy, dz * dz));

        const bool inb = ((unsigned)vx < (unsigned)DVOX) &
                         ((unsigned)vy < (unsigned)DVOX) &
                         ((unsigned)vz < (unsigned)DVOX);

        // ~2/3 of threads exit here before the MUFU + atomic
        if (inb && dist2 <= d2max) {
            float q = dx * dx * irx2
                    + dy * dy * iry2
                    + dz * dz * irz2
                    + rxy * dx * dy
                    + rxz * dx * dz
                    + ryz * dy * dz;
            float w = __expf(-0.5f * q);
            if (w > thr) {
                int flat = (vx * DVOX + vy) * DVOX + vz;
                atomicAdd(&out[flat], val * w);
            }
        }
    }
}

extern "C" void kernel_launch(void* const* d_in, const int* in_sizes, int n_in,
                              void* d_out, int out_size)
{
    const float* paras = (const float*)d_in[0];
    const float* dist  = (const float*)d_in[1];
    const float* thr   = (const float*)d_in[2];
    float* out = (float*)d_out;

    const int N = in_sizes[0] / 10;

    // Zero the (poisoned) output; graph-capturable memset node.
    cudaMemsetAsync(out, 0, (size_t)out_size * sizeof(float), 0);

    splat_kernel<<<N, 352>>>(paras, dist, thr, out, N);
}

// round 2
// speedup vs baseline: 2.0621x; 2.0621x over previous
#include <cuda_runtime.h>
#include <cuda_bf16.h>

// 3D Gaussian splat: N=65536 points -> 256^3 fp32 volume, 7x7x7 window each.
// paras layout (10, N) row-major: px,py,pz,val,rx,rxy,rxz,ry,ryz,rz.
// flat index = (vx*256 + vy)*256 + vz  (z fastest).
//
// R2: one thread per (point, ox, oy); walks the 7 z-voxels with a
// multiplicative exp recurrence (3 __expf per row instead of 7), early-outs
// whole rows on xy-bounds / xy-distance, predicated atomics on consecutive
// addresses.

#define HALF 3
#define DVOX 256
#define PAIRS 49   // 7*7 (ox,oy) pairs per point

__global__ __launch_bounds__(256)
void splat_kernel(const float* __restrict__ paras,
                  const float* __restrict__ dptr,
                  const float* __restrict__ tptr,
                  float* __restrict__ out,
                  int N)
{
    const int tid = blockIdx.x * blockDim.x + threadIdx.x;
    if (tid >= N * PAIRS) return;

    const int pid  = tid / PAIRS;           // magic-mul division
    const int pair = tid - pid * PAIRS;
    const int ox   = pair / 7;
    const int oy   = pair - ox * 7;

    // Point params — threads sharing pid hit the same lines (L1 broadcast)
    const float px  = paras[0 * N + pid];
    const float py  = paras[1 * N + pid];
    const float pz  = paras[2 * N + pid];

    const int cx = (int)floorf(px) - HALF;
    const int cy = (int)floorf(py) - HALF;
    const int cz = (int)floorf(pz) - HALF;

    const int vx = cx + ox;
    const int vy = cy + oy;
    if (((unsigned)vx >= (unsigned)DVOX) | ((unsigned)vy >= (unsigned)DVOX)) return;

    const float dist  = *dptr;
    const float d2max = dist * dist;

    const float dx   = (float)vx - px;
    const float dy   = (float)vy - py;
    const float dxy2 = fmaf(dx, dx, dy * dy);
    if (dxy2 > d2max) return;               // no z can be inside the sphere

    const float val = paras[3 * N + pid];
    const float rx  = paras[4 * N + pid];
    const float rxy = paras[5 * N + pid];
    const float rxz = paras[6 * N + pid];
    const float ry  = paras[7 * N + pid];
    const float ryz = paras[8 * N + pid];
    const float rz  = paras[9 * N + pid];
    const float thr = *tptr;

    const float irx2 = __fdividef(1.0f, rx * rx);
    const float iry2 = __fdividef(1.0f, ry * ry);
    const float irz2 = __fdividef(1.0f, rz * rz);

    // q(dz) = K0 + K1*dz + C*dz^2
    const float C  = irz2;
    const float K1 = fmaf(rxz, dx, ryz * dy);
    const float K0 = dx * dx * irx2 + dy * dy * iry2 + rxy * dx * dy;

    const float dz0 = (float)cz - pz;       // dz at k=0 (in [-4, -3])

    // w(k) = exp(-0.5*q(dz0+k));  w(k+1) = w(k)*r(k);  r(k+1) = r(k)*rho
    float w   = __expf(-0.5f * (K0 + K1 * dz0 + C * dz0 * dz0));
    float r   = __expf(-0.5f * (K1 + C * (2.0f * dz0 + 1.0f)));
    const float rho = __expf(-C);

    const int base = (vx * DVOX + vy) * DVOX;

    #pragma unroll
    for (int k = 0; k < 7; k++) {
        const int   vz    = cz + k;
        const float dz    = dz0 + (float)k;
        const float dist2 = fmaf(dz, dz, dxy2);
        const bool  ok    = ((unsigned)vz < (unsigned)DVOX) &
                            (dist2 <= d2max) & (w > thr);
        if (ok) {
            atomicAdd(&out[base + vz], val * w);
        }
        w *= r;
        r *= rho;
    }
}

extern "C" void kernel_launch(void* const* d_in, const int* in_sizes, int n_in,
                              void* d_out, int out_size)
{
    const float* paras = (const float*)d_in[0];
    const float* dist  = (const float*)d_in[1];
    const float* thr   = (const float*)d_in[2];
    float* out = (float*)d_out;

    const int N = in_sizes[0] / 10;

    cudaMemsetAsync(out, 0, (size_t)out_size * sizeof(float), 0);

    const int total   = N * PAIRS;
    const int threads = 256;
    const int blocks  = (total + threads - 1) / threads;
    splat_kernel<<<blocks, threads>>>(paras, dist, thr, out, N);
}

// round 3
// speedup vs baseline: 3.1662x; 1.5354x over previous
#include <cuda_runtime.h>
#include <cuda_bf16.h>

// 3D Gaussian splat: N=65536 points -> 256^3 fp32 volume, 7x7x7 window each.
// paras layout (10, N) row-major: px,py,pz,val,rx,rxy,rxz,ry,ryz,rz.
// flat index = (vx*256 + vy)*256 + vz  (z fastest).
//
// R3: one thread per (point, ox). 2D exp recurrence: 6 __expf + 3 rcp cover
// all 49 (y,z) voxels. Contributions per z-row are packed into 16B-aligned
// red.global.add.v4.f32 segments (zero-padded; zero-adds are exact identity),
// skipping all-zero segments. Atomic sector-ops drop ~1.8x vs scalar REDs.

#define DVOX 256
#define HALF 3

// GET(i) with literal i folds to a single register or 0.0f at compile time.
#define GET(i) ( ((i) >= 0 && (i) < 7) ? c[(i) < 0 ? 0 : ((i) > 6 ? 6 : (i))] : 0.0f )
// slot s holds contribution for vz = a0 + s, i.e. k = s - p  (p = cz & 3)
#define SLOT(s) ( p == 0 ? GET(s) : p == 1 ? GET((s)-1) : p == 2 ? GET((s)-2) : GET((s)-3) )

__global__ __launch_bounds__(256)
void splat_kernel(const float* __restrict__ paras,
                  const float* __restrict__ dptr,
                  const float* __restrict__ tptr,
                  float* __restrict__ out,
                  int N)
{
    const int tid = blockIdx.x * blockDim.x + threadIdx.x;
    if (tid >= N * 7) return;

    const int pid = tid / 7;               // magic-mul
    const int ox  = tid - pid * 7;

    const float px = paras[0 * N + pid];
    const float py = paras[1 * N + pid];
    const float pz = paras[2 * N + pid];

    const int cx = (int)floorf(px) - HALF;
    const int cy = (int)floorf(py) - HALF;
    const int cz = (int)floorf(pz) - HALF;

    const int vx = cx + ox;
    const float dist  = *dptr;
    const float d2max = dist * dist;

    const float dx  = (float)vx - px;
    const float dx2 = dx * dx;
    // whole x-slice dead: out of bounds or outside sphere for every (y,z)
    if (((unsigned)vx >= (unsigned)DVOX) | (dx2 > d2max)) return;

    const float val = paras[3 * N + pid];
    const float rx  = paras[4 * N + pid];
    const float rxy = paras[5 * N + pid];
    const float rxz = paras[6 * N + pid];
    const float ry  = paras[7 * N + pid];
    const float ryz = paras[8 * N + pid];
    const float rz  = paras[9 * N + pid];
    const float thr = *tptr;

    const float irx2 = __fdividef(1.0f, rx * rx);
    const float iry2 = __fdividef(1.0f, ry * ry);
    const float irz2 = __fdividef(1.0f, rz * rz);

    const float dy0 = (float)cy - py;
    const float dz0 = (float)cz - pz;

    // E(j,k) = -0.5*q(dx, dy0+j, dz0+k)
    // z-recurrence:  w(j,k+1) = w(j,k)*r(j,k),  r(j,k+1) = r(j,k)*rho
    //                r(j,0)   = R00 * Sy^j
    // y-recurrence:  w(j+1,0) = w(j,0)*t(j),    t(j+1)   = t(j)*tau
    const float E00 = -0.5f * (dx2 * irx2 + dy0 * dy0 * iry2 + dz0 * dz0 * irz2
                      + rxy * dx * dy0 + rxz * dx * dz0 + ryz * dy0 * dz0);
    float w_row     = __expf(E00);
    float t         = __expf(-0.5f * ((2.0f * dy0 + 1.0f) * iry2 + rxy * dx + ryz * dz0));
    const float tau = __expf(-iry2);
    float r_row     = __expf(-0.5f * ((2.0f * dz0 + 1.0f) * irz2 + rxz * dx + ryz * dy0));
    const float Sy  = __expf(-0.5f * ryz);
    const float rho = __expf(-irz2);

    const int p  = cz & 3;                  // phase within 16B-aligned segment
    const int a0 = cz - p;                  // aligned z start (can be negative; never
                                            // dereferenced there: those slots are 0)
    const int xbase = vx * (DVOX * DVOX);

    #pragma unroll 1
    for (int j = 0; j < 7; j++) {
        const int   vy   = cy + j;
        const float dy   = dy0 + (float)j;
        const float dxy2 = fmaf(dy, dy, dx2);

        if (((unsigned)vy < (unsigned)DVOX) & (dxy2 <= d2max)) {
            float w = w_row, r = r_row;
            float c[7];
            #pragma unroll
            for (int k = 0; k < 7; k++) {
                const float dz    = dz0 + (float)k;
                const float dist2 = fmaf(dz, dz, dxy2);
                const bool  ok    = ((unsigned)(cz + k) < (unsigned)DVOX) &
                                    (dist2 <= d2max) & (w > thr);
                c[k] = ok ? val * w : 0.0f;
                w *= r;
                r *= rho;
            }

            // Pack into 3 aligned float4 segments (slot s -> vz = a0 + s)
            const float s0 = SLOT(0),  s1 = SLOT(1),  s2  = SLOT(2),  s3  = SLOT(3);
            const float s4 = SLOT(4),  s5 = SLOT(5),  s6  = SLOT(6),  s7  = SLOT(7);
            const float s8 = SLOT(8),  s9 = SLOT(9),  s10 = SLOT(10), s11 = SLOT(11);

            float* line = out + (xbase + vy * DVOX + a0);

            if ((s0 != 0.0f) | (s1 != 0.0f) | (s2 != 0.0f) | (s3 != 0.0f))
                asm volatile("red.global.add.v4.f32 [%0], {%1, %2, %3, %4};"
                             :: "l"(line + 0), "f"(s0), "f"(s1), "f"(s2), "f"(s3)
                             : "memory");
            if ((s4 != 0.0f) | (s5 != 0.0f) | (s6 != 0.0f) | (s7 != 0.0f))
                asm volatile("red.global.add.v4.f32 [%0], {%1, %2, %3, %4};"
                             :: "l"(line + 4), "f"(s4), "f"(s5), "f"(s6), "f"(s7)
                             : "memory");
            if ((s8 != 0.0f) | (s9 != 0.0f) | (s10 != 0.0f) | (s11 != 0.0f))
                asm volatile("red.global.add.v4.f32 [%0], {%1, %2, %3, %4};"
                             :: "l"(line + 8), "f"(s8), "f"(s9), "f"(s10), "f"(s11)
                             : "memory");
        }

        w_row *= t;
        t     *= tau;
        r_row *= Sy;
    }
}

extern "C" void kernel_launch(void* const* d_in, const int* in_sizes, int n_in,
                              void* d_out, int out_size)
{
    const float* paras = (const float*)d_in[0];
    const float* dist  = (const float*)d_in[1];
    const float* thr   = (const float*)d_in[2];
    float* out = (float*)d_out;

    const int N = in_sizes[0] / 10;

    cudaMemsetAsync(out, 0, (size_t)out_size * sizeof(float), 0);

    const int total   = N * 7;
    const int threads = 256;
    const int blocks  = (total + threads - 1) / threads;
    splat_kernel<<<blocks, threads>>>(paras, dist, thr, out, N);
}